// round 8
// baseline (speedup 1.0000x reference)
#include <cuda_runtime.h>
#include <cuda_fp16.h>
#include <cstdint>

#define CC     64
#define KK9    9
#define NH     5
#define NMAX   150000
#define TMM    128
#define MAXT   ((NMAX + TMM - 1) / TMM)     // 1172
#define BN_EPS 1e-5f

// ---------------- device global scratch (no allocations allowed) ----------------
__device__ __half g_f16[(size_t)NMAX * CC];                    // features (fp16)
__device__ __half g_B16[(size_t)NH * KK9 * 4096];              // weights fp16, swizzled
__device__ float g_h[(size_t)NH * NMAX * CC];                  // 192 MB intermediate
__device__ float g_part[(size_t)NH * 2 * CC * MAXT];           // [head][stat][chan][tile]
__device__ float g_scale[NH * CC];
__device__ float g_shift[NH * CC];

// ---------------- helpers ----------------
__device__ __forceinline__ uint32_t smem_u32(const void* p) {
    uint32_t a;
    asm("{ .reg .u64 t; cvta.to.shared.u64 t, %1; cvt.u32.u64 %0, t; }" : "=r"(a) : "l"(p));
    return a;
}
__device__ __forceinline__ void cpa16(uint32_t dst, const void* src, uint32_t sz) {
    asm volatile("cp.async.cg.shared.global [%0], [%1], 16, %2;"
                 :: "r"(dst), "l"(src), "r"(sz) : "memory");
}
__device__ __forceinline__ void cpa_commit() {
    asm volatile("cp.async.commit_group;" ::: "memory");
}
__device__ __forceinline__ void ldx4(uint32_t* r, uint32_t addr) {
    asm volatile("ldmatrix.sync.aligned.m8n8.x4.shared.b16 {%0,%1,%2,%3}, [%4];"
                 : "=r"(r[0]), "=r"(r[1]), "=r"(r[2]), "=r"(r[3]) : "r"(addr));
}
__device__ __forceinline__ void mma_f16(float* c, const uint32_t* a, const uint32_t* b) {
    asm volatile(
        "mma.sync.aligned.m16n8k16.row.col.f32.f16.f16.f32 "
        "{%0,%1,%2,%3}, {%4,%5,%6,%7}, {%8,%9}, {%0,%1,%2,%3};"
        : "+f"(c[0]), "+f"(c[1]), "+f"(c[2]), "+f"(c[3])
        : "r"(a[0]), "r"(a[1]), "r"(a[2]), "r"(a[3]), "r"(b[0]), "r"(b[1]));
}

// ---------------- prep kernels ----------------
__global__ __launch_bounds__(256) void prep_feat(const float* __restrict__ f, int n) {
    int i = blockIdx.x * blockDim.x + threadIdx.x;
    if (i >= n) return;
    g_f16[i] = __float2half(f[i]);
}

// W3 [h][k][c][o] -> slabs [h*9+k][n=o][k=c] fp16, 16B-xor swizzled for ldmatrix
__global__ __launch_bounds__(256) void prep_w3(const float* __restrict__ w) {
    int i = blockIdx.x * blockDim.x + threadIdx.x;
    if (i >= NH * KK9 * 4096) return;
    int slab = i >> 12;
    int r = i & 4095;
    int c = r >> 6;        // K index
    int o = r & 63;        // N index
    int e = (o * 8 + ((c >> 3) ^ (o & 7))) * 8 + (c & 7);
    g_B16[(size_t)slab * 4096 + e] = __float2half(w[i]);
}

// ---------------- pass1: tile-persistent fp16 mma.sync gather-GEMM ----------------
// SMEM: A: 9 slabs x 16KB = 144KB at 0   (gathered ONCE, reused by all 5 heads)
//       B: 3 bufs x 8KB = 24KB at 147456 (1-ahead prefetch ring)
//       red: 2KB at 172032
#define SM_A    0u
#define SM_B    147456u
#define SM_RED  172032u
#define SM_TOT  174080u

__device__ __forceinline__ void gatherA(uint32_t sb, int k,
                                        const int* __restrict__ nbr,
                                        int m0, int Nv)
{
    const int t   = threadIdx.x;
    const int row = t >> 1;          // 128 rows, 2 threads each
    const int m   = m0 + row;
    int idx = -1;
    if (m < Nv) idx = __ldg(&nbr[(size_t)m * KK9 + k]);
    uint32_t sz = (idx >= 0) ? 16u : 0u;
    int ic = (idx >= 0) ? idx : 0;
    const char* src = (const char*)g_f16 + (size_t)ic * 128 + (t & 1) * 64;
    uint32_t dbase = sb + SM_A + (uint32_t)k * 16384u + (uint32_t)row * 128u;
    #pragma unroll
    for (int j = 0; j < 4; ++j) {
        int c16 = (t & 1) * 4 + j;
        uint32_t off = (uint32_t)((c16 ^ (row & 7)) << 4);
        cpa16(dbase + off, src + j * 16, sz);
    }
}

__device__ __forceinline__ void copyB(uint32_t sb, int buf, int slab) {
    const int t = threadIdx.x;
    const char* src = (const char*)g_B16 + (size_t)slab * 8192;
    uint32_t dst = sb + SM_B + (uint32_t)buf * 8192u;
    #pragma unroll
    for (int j = 0; j < 2; ++j) {
        int i = t + j * 256;
        cpa16(dst + (uint32_t)i * 16u, src + (size_t)i * 16, 16u);
    }
}

__device__ __forceinline__ void slab_mma(uint32_t Ak, uint32_t Bb,
                                         const uint32_t aoff[2][4],
                                         const uint32_t boff[2][4],
                                         float acc[2][4][4])
{
    #pragma unroll
    for (int kk = 0; kk < 4; ++kk) {
        uint32_t ah[2][4];
        #pragma unroll
        for (int mf = 0; mf < 2; ++mf) ldx4(ah[mf], Ak + aoff[mf][kk]);
        uint32_t bh[2][4];
        #pragma unroll
        for (int p = 0; p < 2; ++p)   ldx4(bh[p], Bb + boff[p][kk]);
        #pragma unroll
        for (int mf = 0; mf < 2; ++mf)
            #pragma unroll
            for (int nf = 0; nf < 4; ++nf)
                mma_f16(acc[mf][nf], ah[mf], &bh[nf >> 1][(nf & 1) * 2]);
    }
}

__global__ __launch_bounds__(256, 1) void pass1_mma(
    const int* __restrict__ nbr, int Nv, int ntiles)
{
    extern __shared__ char smem[];
    const uint32_t sb = smem_u32(smem);
    const int tid  = threadIdx.x;
    const int wid  = tid >> 5;
    const int lane = tid & 31;
    const int m0   = blockIdx.x * TMM;

    const int wm = wid & 3;            // 4 M-warps (32 rows each)
    const int wn = wid >> 2;           // 2 N-warps (32 cols each)
    const int warpM0 = wm * 32;
    const int warpN0 = wn * 32;

    // precompute ldmatrix fragment offsets (lane-dependent, slab-invariant)
    uint32_t aoff[2][4], boff[2][4];
    #pragma unroll
    for (int kk = 0; kk < 4; ++kk) {
        #pragma unroll
        for (int mf = 0; mf < 2; ++mf) {
            int rr = warpM0 + mf * 16 + (lane & 7) + ((lane >> 3) & 1) * 8;
            int c16 = kk * 2 + (lane >> 4);
            aoff[mf][kk] = (uint32_t)(rr * 128 + ((c16 ^ (rr & 7)) << 4));
        }
        #pragma unroll
        for (int p = 0; p < 2; ++p) {
            int nn = warpN0 + p * 16 + (lane & 7) + ((lane >> 4) << 3);
            int c16 = kk * 2 + ((lane >> 3) & 1);
            boff[p][kk] = (uint32_t)(nn * 128 + ((c16 ^ (nn & 7)) << 4));
        }
    }

    float acc[2][4][4];
    #pragma unroll
    for (int i = 0; i < 2; ++i)
        #pragma unroll
        for (int j = 0; j < 4; ++j)
            #pragma unroll
            for (int q = 0; q < 4; ++q) acc[i][j][q] = 0.f;

    // prologue: 9 A slabs + B slab 0, then wait for ALL of them.
    // (cp.async groups retire in commit order; B0 is the last group, so the
    //  only wait that guarantees it is a full drain. ~2us/CTA-wave, once.)
    #pragma unroll
    for (int k = 0; k < KK9; ++k) { gatherA(sb, k, nbr, m0, Nv); cpa_commit(); }
    copyB(sb, 0, 0); cpa_commit();
    asm volatile("cp.async.wait_group 0;" ::: "memory");
    __syncthreads();

    float* red = (float*)(smem + SM_RED);

    // 45 MMA phases: jj = h*9 + k. B ring: buf jj%3. Epilogue after each head.
    #pragma unroll 1
    for (int jj = 0; jj < NH * KK9; ++jj) {
        if (jj + 1 < NH * KK9) {           // prefetch next B (1 ahead)
            copyB(sb, (jj + 1) % 3, jj + 1); cpa_commit();
            if (jj > 0)
                asm volatile("cp.async.wait_group 1;" ::: "memory");  // B_jj retired
        } else if (jj > 0) {
            asm volatile("cp.async.wait_group 0;" ::: "memory");
        }
        __syncthreads();   // B_jj visible to all; ring buf (jj+1)%3 free of readers
        slab_mma(sb + SM_A + (uint32_t)(jj % KK9) * 16384u,
                 sb + SM_B + (uint32_t)(jj % 3) * 8192u, aoff, boff, acc);

        if (jj % KK9 == KK9 - 1) {
            // ---- epilogue for head h: write g_h + BN partials, reset acc ----
            const int h = jj / KK9;
            float* hb = g_h + (size_t)h * Nv * CC;
            #pragma unroll
            for (int mf = 0; mf < 2; ++mf)
                #pragma unroll
                for (int nf = 0; nf < 4; ++nf) {
                    int r = m0 + warpM0 + mf * 16 + (lane >> 2);
                    int c = warpN0 + nf * 8 + (lane & 3) * 2;
                    float* a = acc[mf][nf];
                    if (r < Nv)     *(float2*)(hb + (size_t)r * CC + c)       = make_float2(a[0], a[1]);
                    if (r + 8 < Nv) *(float2*)(hb + (size_t)(r + 8) * CC + c) = make_float2(a[2], a[3]);
                }
            __syncthreads();   // previous red readers done
            #pragma unroll
            for (int nf = 0; nf < 4; ++nf) {
                float s0 = 0.f, s1 = 0.f, q0 = 0.f, q1 = 0.f;
                #pragma unroll
                for (int mf = 0; mf < 2; ++mf) {
                    float* a = acc[mf][nf];
                    s0 += a[0] + a[2];  q0 += a[0] * a[0] + a[2] * a[2];
                    s1 += a[1] + a[3];  q1 += a[1] * a[1] + a[3] * a[3];
                }
                #pragma unroll
                for (int sh = 4; sh < 32; sh <<= 1) {
                    s0 += __shfl_xor_sync(0xffffffffu, s0, sh);
                    s1 += __shfl_xor_sync(0xffffffffu, s1, sh);
                    q0 += __shfl_xor_sync(0xffffffffu, q0, sh);
                    q1 += __shfl_xor_sync(0xffffffffu, q1, sh);
                }
                if (lane < 4) {
                    int c = warpN0 + nf * 8 + lane * 2;
                    red[(wm * 2 + 0) * 64 + c]     = s0;
                    red[(wm * 2 + 0) * 64 + c + 1] = s1;
                    red[(wm * 2 + 1) * 64 + c]     = q0;
                    red[(wm * 2 + 1) * 64 + c + 1] = q1;
                }
            }
            __syncthreads();
            if (tid < 128) {
                int w = tid >> 6, col = tid & 63;
                float v = red[(0 * 2 + w) * 64 + col] + red[(1 * 2 + w) * 64 + col]
                        + red[(2 * 2 + w) * 64 + col] + red[(3 * 2 + w) * 64 + col];
                g_part[((((size_t)h * 2 + w) * CC) + col) * MAXT + blockIdx.x] = v;
            }
            #pragma unroll
            for (int i = 0; i < 2; ++i)
                #pragma unroll
                for (int j = 0; j < 4; ++j)
                    #pragma unroll
                    for (int q = 0; q < 4; ++q) acc[i][j][q] = 0.f;
        }
    }
}

// ---------------- BN stats reduce (coalesced + vectorized over tiles) ----------------
__global__ __launch_bounds__(256) void reduce_stats(
    const float* __restrict__ gamma, const float* __restrict__ beta,
    int Nv, int ntiles)
{
    int gw   = (blockIdx.x * blockDim.x + threadIdx.x) >> 5;
    int lane = threadIdx.x & 31;
    if (gw >= NH * CC) return;
    int head = gw / CC, c = gw % CC;
    const float* ps = g_part + (((size_t)head * 2 + 0) * CC + c) * MAXT;
    const float* pq = g_part + (((size_t)head * 2 + 1) * CC + c) * MAXT;
    float s = 0.f, q = 0.f;
    int nt4 = ntiles >> 2;
    const float4* ps4 = (const float4*)ps;
    const float4* pq4 = (const float4*)pq;
    for (int i = lane; i < nt4; i += 32) {
        float4 a = ps4[i], b = pq4[i];
        s += (a.x + a.y) + (a.z + a.w);
        q += (b.x + b.y) + (b.z + b.w);
    }
    for (int i = nt4 * 4 + lane; i < ntiles; i += 32) { s += ps[i]; q += pq[i]; }
    #pragma unroll
    for (int sh = 16; sh > 0; sh >>= 1) {
        s += __shfl_down_sync(0xffffffffu, s, sh);
        q += __shfl_down_sync(0xffffffffu, q, sh);
    }
    if (lane == 0) {
        float invN = 1.f / (float)Nv;
        float mean = s * invN;
        float var  = q * invN - mean * mean;
        float inv  = rsqrtf(var + BN_EPS);
        float sc   = inv * gamma[gw];
        g_scale[gw] = sc;
        g_shift[gw] = beta[gw] - mean * sc;
    }
}

// ---------------- pass 2: BN + ReLU + 1x1 convs ----------------
__global__ __launch_bounds__(256) void pass2_kernel(
    const float* __restrict__ W1_0, const float* __restrict__ b1_0,
    const float* __restrict__ W1_1, const float* __restrict__ b1_1,
    const float* __restrict__ W1_2, const float* __restrict__ b1_2,
    const float* __restrict__ W1_3, const float* __restrict__ b1_3,
    const float* __restrict__ W1_4, const float* __restrict__ b1_4,
    float* __restrict__ out, int Nv)
{
    int wid  = (blockIdx.x * blockDim.x + threadIdx.x) >> 5;
    int lane = threadIdx.x & 31;
    if (wid >= NH * Nv) return;
    int head = wid / Nv;
    int n    = wid - head * Nv;

    size_t base = ((size_t)head * Nv + n) * CC;
    int c0 = lane, c1 = lane + 32;
    float h0 = g_h[base + c0];
    float h1 = g_h[base + c1];
    int s0 = head * CC + c0, s1 = head * CC + c1;
    float y0 = fmaxf(0.f, fmaf(h0, g_scale[s0], g_shift[s0]));
    float y1 = fmaxf(0.f, fmaf(h1, g_scale[s1], g_shift[s1]));

    const float* W1; const float* b1; int oc; int off;
    switch (head) {
        case 0:  W1 = W1_0; b1 = b1_0; oc = 3; off = 0; break;
        case 1:  W1 = W1_1; b1 = b1_1; oc = 2; off = 3; break;
        case 2:  W1 = W1_2; b1 = b1_2; oc = 1; off = 5; break;
        case 3:  W1 = W1_3; b1 = b1_3; oc = 3; off = 6; break;
        default: W1 = W1_4; b1 = b1_4; oc = 2; off = 9; break;
    }
    size_t ob = (size_t)off * Nv + (size_t)n * oc;
    for (int o = 0; o < oc; ++o) {
        float p = y0 * W1[c0 * oc + o] + y1 * W1[c1 * oc + o];
        #pragma unroll
        for (int s = 16; s > 0; s >>= 1)
            p += __shfl_down_sync(0xffffffffu, p, s);
        if (lane == 0) out[ob + o] = p + b1[o];
    }
}

// ---------------------------------------------------------------------------
extern "C" void kernel_launch(void* const* d_in, const int* in_sizes, int n_in,
                              void* d_out, int out_size)
{
    const float* feat  = (const float*)d_in[0];
    const int*   nbr   = (const int*)  d_in[1];
    const float* W3    = (const float*)d_in[2];
    const float* gamma = (const float*)d_in[3];
    const float* beta  = (const float*)d_in[4];

    int Nv = in_sizes[0] / CC;
    if (Nv > NMAX) Nv = NMAX;
    int ntiles = (Nv + TMM - 1) / TMM;

    cudaFuncSetAttribute(pass1_mma, cudaFuncAttributeMaxDynamicSharedMemorySize, SM_TOT);

    int nf = Nv * CC;
    prep_feat<<<(nf + 255) / 256, 256>>>(feat, nf);
    prep_w3<<<(NH * KK9 * 4096 + 255) / 256, 256>>>(W3);

    pass1_mma<<<ntiles, 256, SM_TOT>>>(nbr, Nv, ntiles);

    reduce_stats<<<(NH * CC * 32 + 255) / 256, 256>>>(gamma, beta, Nv, ntiles);

    long long nthreads = (long long)NH * Nv * 32;
    int blocks2 = (int)((nthreads + 255) / 256);
    pass2_kernel<<<blocks2, 256>>>(
        (const float*)d_in[5],  (const float*)d_in[6],
        (const float*)d_in[7],  (const float*)d_in[8],
        (const float*)d_in[9],  (const float*)d_in[10],
        (const float*)d_in[11], (const float*)d_in[12],
        (const float*)d_in[13], (const float*)d_in[14],
        (float*)d_out, Nv);
}